// round 8
// baseline (speedup 1.0000x reference)
#include <cuda_runtime.h>
#include <cuda_bf16.h>
#include <math_constants.h>

// Problem constants (fixed by the dataset)
#define NNODES 50000
#define NDIM   64
#define NEDGES 800000

// -------- device scratch (no allocation allowed) --------
__device__ int   g_deg[NNODES];
__device__ int   g_cursor[NNODES];
__device__ int   g_starts[NNODES];
__device__ int   g_total;
__device__ int2  g_edge[NEDGES];    // (src_row, bitcast(weight)) packed

// -------- kernel 1: zero counters --------
__global__ void k_zero() {
    int i = blockIdx.x * blockDim.x + threadIdx.x;
    if (i < NNODES) g_deg[i] = 0;
    if (i == 0) g_total = 0;
}

// -------- kernel 2: count in-degree --------
__global__ void k_count(const int* __restrict__ edge_index) {
    int e = blockIdx.x * blockDim.x + threadIdx.x;
    if (e < NEDGES) {
        int dst = edge_index[NEDGES + e];   // edge_index[1, e]
        atomicAdd(&g_deg[dst], 1);
    }
}

// -------- kernel 3: segment offsets (block scan + global atomic base) --------
// Also pre-initializes g_cursor to the segment start so the scatter kernel
// needs no separate g_starts read. Segment ordering across blocks is
// nondeterministic, but segments are disjoint and the median is
// order-invariant -> output deterministic.
#define OFF_BS 256
__global__ void k_offsets() {
    __shared__ int sh[OFF_BS];
    __shared__ int base;
    int tid = threadIdx.x;
    int gid = blockIdx.x * OFF_BS + tid;
    int v = (gid < NNODES) ? g_deg[gid] : 0;
    sh[tid] = v;
    __syncthreads();
    for (int off = 1; off < OFF_BS; off <<= 1) {
        int t = (tid >= off) ? sh[tid - off] : 0;
        __syncthreads();
        sh[tid] += t;
        __syncthreads();
    }
    if (tid == OFF_BS - 1) base = atomicAdd(&g_total, sh[tid]);
    __syncthreads();
    if (gid < NNODES) {
        int st = base + sh[tid] - v;
        g_starts[gid] = st;
        g_cursor[gid] = st;
    }
}

// -------- kernel 4: scatter (counting sort by destination) --------
// Cursor already holds the segment start: single atomic gives the slot.
__global__ void k_scatter(const int* __restrict__ edge_index,
                          const float* __restrict__ edge_weight) {
    int e = blockIdx.x * blockDim.x + threadIdx.x;
    if (e >= NEDGES) return;
    int src = edge_index[e];
    int dst = edge_index[NEDGES + e];
    float w = edge_weight[e];
    int p = atomicAdd(&g_cursor[dst], 1);
    g_edge[p] = make_int2(src, __float_as_int(w));
}

// -------- pruned Batcher odd-even merge network (element type T) --------
__device__ __forceinline__ void cas_e(float& a, float& b) {
    float lo = fminf(a, b);
    float hi = fmaxf(a, b);
    a = lo; b = hi;
}
__device__ __forceinline__ void cas_e(float2& a, float2& b) {
    float lox = fminf(a.x, b.x), hix = fmaxf(a.x, b.x);
    float loy = fminf(a.y, b.y), hiy = fmaxf(a.y, b.y);
    a.x = lox; b.x = hix;
    a.y = loy; b.y = hiy;
}

template<typename T, int D, int LO, int N, int R>
struct OEMergeD {
    static __device__ __forceinline__ void run(T* v) {
        constexpr int M = R * 2;
        if constexpr (LO >= D) return;
        else if constexpr (M < N) {
            OEMergeD<T, D, LO, N, M>::run(v);
            OEMergeD<T, D, LO + R, N, M>::run(v);
#pragma unroll
            for (int i = LO + R; i + R < LO + N; i += M)
                if (i + R < D) cas_e(v[i], v[i + R]);   // folds at compile time
        } else {
            if constexpr (LO + R < D) cas_e(v[LO], v[LO + R]);
        }
    }
};

template<typename T, int D, int LO, int N>
struct OESortD {
    static __device__ __forceinline__ void run(T* v) {
        if constexpr (LO >= D || N <= 1) return;
        else {
            constexpr int M = N / 2;
            OESortD<T, D, LO, M>::run(v);
            OESortD<T, D, LO + M, M>::run(v);
            OEMergeD<T, D, LO, N, 1>::run(v);
        }
    }
};

// -------- gather(float2) + pruned sort + k-select for degree bucket D --------
// Thread handles 2 adjacent channels; x2 = x viewed as float2 rows of 32.
template<int D>
__device__ __forceinline__ float2 median_reg2(const int2* __restrict__ stage,
                                              const float2* __restrict__ x2,
                                              int lane, int deg, int k) {
    constexpr int P = (D <= 8) ? 8 : (D <= 16) ? 16 : 32;   // parent pow2 network
    float2 v[D];
#pragma unroll
    for (int j = 0; j < D; j++) {
        if (j < deg) {
            int2 e = stage[j];
            float w = __int_as_float(e.y);
            float2 xv = x2[e.x * (NDIM / 2) + lane];
            v[j].x = xv.x * w;
            v[j].y = xv.y * w;
        } else {
            v[j].x = CUDART_INF_F;
            v[j].y = CUDART_INF_F;
        }
    }
    OESortD<float2, D, 0, P>::run(v);
    float2 r = v[0];
#pragma unroll
    for (int i = 1; i < D; i++) {
        r.x = (k == i) ? v[i].x : r.x;
        r.y = (k == i) ? v[i].y : r.y;
    }
    return r;
}

// -------- kernel 5: per-node per-channel lower median --------
// ONE warp per node; each thread owns 2 adjacent channels (float2 loads ->
// each edge row is a single fully-coalesced 256B warp transaction). Warps
// are independent (__syncwarp only).
#define NODES_PER_BLK 8
__global__ void __launch_bounds__(32 * NODES_PER_BLK)
k_median(const float* __restrict__ x, float* __restrict__ out) {
    __shared__ int2 stage_s[NODES_PER_BLK][32];

    int n = blockIdx.x * NODES_PER_BLK + threadIdx.y;
    int lane = threadIdx.x;
    if (n >= NNODES) return;

    float2* out2 = reinterpret_cast<float2*>(out) + n * (NDIM / 2);
    int deg = g_deg[n];
    if (deg == 0) {
        out2[lane] = make_float2(0.0f, 0.0f);
        return;
    }
    int s = g_starts[n];
    int k = (deg - 1) >> 1;
    const float2* x2 = reinterpret_cast<const float2*>(x);

    if (deg <= 32) {
        if (lane < deg) stage_s[threadIdx.y][lane] = g_edge[s + lane];
        __syncwarp();
        const int2* st = stage_s[threadIdx.y];

        float2 med;
        if      (deg <= 8)  med = median_reg2<8> (st, x2, lane, deg, k);
        else if (deg <= 12) med = median_reg2<12>(st, x2, lane, deg, k);
        else if (deg <= 16) med = median_reg2<16>(st, x2, lane, deg, k);
        else if (deg <= 20) med = median_reg2<20>(st, x2, lane, deg, k);
        else if (deg <= 24) med = median_reg2<24>(st, x2, lane, deg, k);
        else if (deg <= 28) med = median_reg2<28>(st, x2, lane, deg, k);
        else                med = median_reg2<32>(st, x2, lane, deg, k);
        out2[lane] = med;
    } else {
        // Rare path (P(deg>32) ~ 1e-4 per node): global rank-count selection,
        // independently for the two channels this thread owns.
        float2 med = make_float2(0.0f, 0.0f);
        bool fx = false, fy = false;
        for (int i = 0; i < deg && !(fx && fy); i++) {
            int2 ei = g_edge[s + i];
            float wi = __int_as_float(ei.y);
            float2 xi = x2[ei.x * (NDIM / 2) + lane];
            float vix = xi.x * wi, viy = xi.y * wi;
            int lx = 0, ex = 0, ly = 0, ey = 0;
            for (int j = 0; j < deg; j++) {
                int2 ej = g_edge[s + j];
                float wj = __int_as_float(ej.y);
                float2 xj = x2[ej.x * (NDIM / 2) + lane];
                float vjx = xj.x * wj, vjy = xj.y * wj;
                lx += (vjx < vix); ex += (vjx == vix);
                ly += (vjy < viy); ey += (vjy == viy);
            }
            if (!fx && lx <= k && k < lx + ex) { med.x = vix; fx = true; }
            if (!fy && ly <= k && k < ly + ey) { med.y = viy; fy = true; }
        }
        out2[lane] = med;
    }
}

extern "C" void kernel_launch(void* const* d_in, const int* in_sizes, int n_in,
                              void* d_out, int out_size) {
    const float* x           = (const float*)d_in[0];
    const int*   edge_index  = (const int*)d_in[1];
    const float* edge_weight = (const float*)d_in[2];
    float*       out         = (float*)d_out;

    (void)in_sizes; (void)n_in; (void)out_size;

    k_zero   <<<(NNODES + 255) / 256, 256>>>();
    k_count  <<<(NEDGES + 255) / 256, 256>>>(edge_index);
    k_offsets<<<(NNODES + OFF_BS - 1) / OFF_BS, OFF_BS>>>();
    k_scatter<<<(NEDGES + 255) / 256, 256>>>(edge_index, edge_weight);

    dim3 mblk(32, NODES_PER_BLK);
    k_median <<<(NNODES + NODES_PER_BLK - 1) / NODES_PER_BLK, mblk>>>(x, out);
}

// round 10
// speedup vs baseline: 1.1376x; 1.1376x over previous
#include <cuda_runtime.h>
#include <cuda_bf16.h>
#include <math_constants.h>

// Problem constants (fixed by the dataset)
#define NNODES 50000
#define NDIM   64
#define NEDGES 800000

// -------- device scratch (no allocation allowed) --------
__device__ int   g_deg[NNODES];
__device__ int   g_cursor[NNODES];
__device__ int   g_starts[NNODES];
__device__ int   g_total;
__device__ int2  g_edge[NEDGES];    // (src_row, bitcast(weight)) packed

// -------- kernel 1: zero counters --------
__global__ void k_zero() {
    int i = blockIdx.x * blockDim.x + threadIdx.x;
    if (i < NNODES) g_deg[i] = 0;
    if (i == 0) g_total = 0;
}

// -------- kernel 2: count in-degree (4 edges/thread, vectorized) --------
__global__ void k_count(const int* __restrict__ edge_index) {
    int t = blockIdx.x * blockDim.x + threadIdx.x;
    if (t >= NEDGES / 4) return;
    int4 dst = reinterpret_cast<const int4*>(edge_index + NEDGES)[t];
    atomicAdd(&g_deg[dst.x], 1);
    atomicAdd(&g_deg[dst.y], 1);
    atomicAdd(&g_deg[dst.z], 1);
    atomicAdd(&g_deg[dst.w], 1);
}

// -------- kernel 3: segment offsets (block scan + global atomic base) --------
// Also pre-initializes g_cursor to the segment start. Segment ordering across
// blocks is nondeterministic, but segments are disjoint and the median is
// order-invariant -> output deterministic.
#define OFF_BS 256
__global__ void k_offsets() {
    __shared__ int sh[OFF_BS];
    __shared__ int base;
    int tid = threadIdx.x;
    int gid = blockIdx.x * OFF_BS + tid;
    int v = (gid < NNODES) ? g_deg[gid] : 0;
    sh[tid] = v;
    __syncthreads();
    for (int off = 1; off < OFF_BS; off <<= 1) {
        int t = (tid >= off) ? sh[tid - off] : 0;
        __syncthreads();
        sh[tid] += t;
        __syncthreads();
    }
    if (tid == OFF_BS - 1) base = atomicAdd(&g_total, sh[tid]);
    __syncthreads();
    if (gid < NNODES) {
        int st = base + sh[tid] - v;
        g_starts[gid] = st;
        g_cursor[gid] = st;
    }
}

// -------- kernel 4: scatter (4 edges/thread, vectorized loads) --------
__global__ void k_scatter(const int* __restrict__ edge_index,
                          const float* __restrict__ edge_weight) {
    int t = blockIdx.x * blockDim.x + threadIdx.x;
    if (t >= NEDGES / 4) return;
    int4   src = reinterpret_cast<const int4*>(edge_index)[t];
    int4   dst = reinterpret_cast<const int4*>(edge_index + NEDGES)[t];
    float4 w   = reinterpret_cast<const float4*>(edge_weight)[t];
    int p0 = atomicAdd(&g_cursor[dst.x], 1);
    int p1 = atomicAdd(&g_cursor[dst.y], 1);
    int p2 = atomicAdd(&g_cursor[dst.z], 1);
    int p3 = atomicAdd(&g_cursor[dst.w], 1);
    g_edge[p0] = make_int2(src.x, __float_as_int(w.x));
    g_edge[p1] = make_int2(src.y, __float_as_int(w.y));
    g_edge[p2] = make_int2(src.z, __float_as_int(w.z));
    g_edge[p3] = make_int2(src.w, __float_as_int(w.w));
}

// -------- pruned Batcher odd-even merge network --------
// Ascending comparators only (lo -> lower wire). With +inf on wires >= deg,
// those wires hold +inf forever, so every comparator with high wire >= D can
// be removed at compile time -> valid D-element network, v[] needs D regs.
__device__ __forceinline__ void cas_f(float& a, float& b) {
    float lo = fminf(a, b);
    float hi = fmaxf(a, b);
    a = lo; b = hi;
}

template<int D, int LO, int N, int R>
struct OEMergeD {
    static __device__ __forceinline__ void run(float* v) {
        constexpr int M = R * 2;
        if constexpr (LO >= D) return;
        else if constexpr (M < N) {
            OEMergeD<D, LO, N, M>::run(v);
            OEMergeD<D, LO + R, N, M>::run(v);
#pragma unroll
            for (int i = LO + R; i + R < LO + N; i += M)
                if (i + R < D) cas_f(v[i], v[i + R]);   // folds at compile time
        } else {
            if constexpr (LO + R < D) cas_f(v[LO], v[LO + R]);
        }
    }
};

template<int D, int LO, int N>
struct OESortD {
    static __device__ __forceinline__ void run(float* v) {
        if constexpr (LO >= D || N <= 1) return;
        else {
            constexpr int M = N / 2;
            OESortD<D, LO, M>::run(v);
            OESortD<D, LO + M, M>::run(v);
            OEMergeD<D, LO, N, 1>::run(v);
        }
    }
};

// -------- register gather + pruned sort + k-select for degree bucket D --------
template<int D>
__device__ __forceinline__ float median_reg(const int2* __restrict__ stage,
                                            const float* __restrict__ x,
                                            int d, int deg, int k) {
    constexpr int P = (D <= 8) ? 8 : (D <= 16) ? 16 : 32;   // parent pow2 network
    float v[D];
#pragma unroll
    for (int j = 0; j < D; j++) {
        if (j < deg) {
            int2 e = stage[j];
            v[j] = x[e.x * NDIM + d] * __int_as_float(e.y);
        } else {
            v[j] = CUDART_INF_F;
        }
    }
    OESortD<D, 0, P>::run(v);
    float r = v[0];
#pragma unroll
    for (int i = 1; i < D; i++) r = (k == i) ? v[i] : r;
    return r;
}

// -------- kernel 5: per-node per-channel lower median --------
// 4 nodes/block, 2 warps/node. Warps are fully independent: each warp stages
// its node's edge list into its own smem slice (__syncwarp only, no block
// barriers), so degree buckets can differ freely across warps.
#define NODES_PER_BLK 4
__global__ void __launch_bounds__(NDIM * NODES_PER_BLK)
k_median(const float* __restrict__ x, float* __restrict__ out) {
    __shared__ int2 stage_s[NODES_PER_BLK * 2][32];

    int n = blockIdx.x * NODES_PER_BLK + threadIdx.y;
    int d = threadIdx.x;
    if (n >= NNODES) return;

    int deg = g_deg[n];
    if (deg == 0) {
        out[n * NDIM + d] = 0.0f;
        return;
    }
    int s = g_starts[n];
    int k = (deg - 1) >> 1;

    if (deg <= 32) {
        int wi   = threadIdx.y * 2 + (d >> 5);
        int lane = d & 31;
        if (lane < deg) stage_s[wi][lane] = g_edge[s + lane];
        __syncwarp();
        const int2* st = stage_s[wi];

        float med;
        if      (deg <= 8)  med = median_reg<8> (st, x, d, deg, k);
        else if (deg <= 12) med = median_reg<12>(st, x, d, deg, k);
        else if (deg <= 16) med = median_reg<16>(st, x, d, deg, k);
        else if (deg <= 20) med = median_reg<20>(st, x, d, deg, k);
        else if (deg <= 24) med = median_reg<24>(st, x, d, deg, k);
        else if (deg <= 28) med = median_reg<28>(st, x, d, deg, k);
        else                med = median_reg<32>(st, x, d, deg, k);
        out[n * NDIM + d] = med;
    } else {
        // Rare path (P(deg>32) ~ 1e-4 per node): global rank-count selection.
        float med = 0.0f;
        for (int i = 0; i < deg; i++) {
            int2 ei = g_edge[s + i];
            float vi = x[ei.x * NDIM + d] * __int_as_float(ei.y);
            int less = 0, eq = 0;
            for (int j = 0; j < deg; j++) {
                int2 ej = g_edge[s + j];
                float vj = x[ej.x * NDIM + d] * __int_as_float(ej.y);
                less += (vj < vi);
                eq   += (vj == vi);
            }
            if (less <= k && k < less + eq) { med = vi; break; }
        }
        out[n * NDIM + d] = med;
    }
}

extern "C" void kernel_launch(void* const* d_in, const int* in_sizes, int n_in,
                              void* d_out, int out_size) {
    const float* x           = (const float*)d_in[0];
    const int*   edge_index  = (const int*)d_in[1];
    const float* edge_weight = (const float*)d_in[2];
    float*       out         = (float*)d_out;

    (void)in_sizes; (void)n_in; (void)out_size;

    k_zero   <<<(NNODES + 255) / 256, 256>>>();
    k_count  <<<(NEDGES / 4 + 255) / 256, 256>>>(edge_index);
    k_offsets<<<(NNODES + OFF_BS - 1) / OFF_BS, OFF_BS>>>();
    k_scatter<<<(NEDGES / 4 + 255) / 256, 256>>>(edge_index, edge_weight);

    dim3 mblk(NDIM, NODES_PER_BLK);
    k_median <<<(NNODES + NODES_PER_BLK - 1) / NODES_PER_BLK, mblk>>>(x, out);
}